// round 1
// baseline (speedup 1.0000x reference)
#include <cuda_runtime.h>

#define N_ANCHS   100800
#define NCLS      80
#define IMG_W     1280
#define K_DETS    300
#define OUTSZ     224
#define CAND_CAP  16384
#define SORT_N    2048
#define NBUCK     1024
#define CH_ELEMS  (OUTSZ*OUTSZ)        // 50176
#define CROP_ELEMS (3*CH_ELEMS)        // 150528

// Output layout (flattened tuple, fp32):
//   [0,1200)          final_boxes  (300,4)
//   [1200,1500)       final_scores (300)
//   [1500,1800)       final_classes(300)
//   [1800,45310728)   all_crops    (301,3,224,224)
//   [45310728,45311028) keep       (300)
#define OFF_BOXES   0
#define OFF_SCORES  1200
#define OFF_CLASSES 1500
#define OFF_CROPS   1800
#define OFF_KEEP    45310728

__device__ unsigned long long g_cand[CAND_CAP];
__device__ int   g_cand_cnt;
__device__ int   g_hist[NBUCK];
__device__ unsigned char g_cls[N_ANCHS];
__device__ int   g_top_idx[K_DETS];
__device__ float g_top_score[K_DETS];
__device__ float4 g_fbox[K_DETS];
__device__ int   g_keep[K_DETS];

__constant__ float c_mean[3] = {0.485f, 0.456f, 0.406f};
__constant__ float c_istd[3] = {1.0f/0.229f, 1.0f/0.224f, 1.0f/0.225f};

// ---------------------------------------------------------------------------
__global__ void k_init() {
    int t = threadIdx.x;
    if (t == 0) g_cand_cnt = 0;
    for (int b = t; b < NBUCK; b += blockDim.x) g_hist[b] = 0;
}

// ---------------------------------------------------------------------------
// Per-anchor: max/argmax over 80 class logits (channels 5..84), filter by
// score > 0.1 and class in allowed set; emit sortable key for candidates.
__global__ void k_score(const float* __restrict__ raw) {
    int i = blockIdx.x * blockDim.x + threadIdx.x;
    if (i >= N_ANCHS) return;
    const float* lg = raw + 5 * N_ANCHS;
    float best = lg[i];
    int bc = 0;
    #pragma unroll 4
    for (int c = 1; c < NCLS; c++) {
        float v = lg[c * N_ANCHS + i];
        if (v > best) { best = v; bc = c; }   // first-max wins (matches argmax)
    }
    g_cls[i] = (unsigned char)bc;
    int cls = bc + 1;
    bool allowed = (cls==1)|(cls==2)|(cls==3)|(cls==4)|(cls==6)|(cls==8)|
                   (cls==17)|(cls==18)|(cls==44);
    if (allowed && best > 0.1f) {
        int b = (int)(best * 170.0f);
        b = max(0, min(NBUCK - 1, b));
        atomicAdd(&g_hist[b], 1);
        int pos = atomicAdd(&g_cand_cnt, 1);
        if (pos < CAND_CAP) {
            // key: score bits (positive float -> monotone uint) | inverted index
            // descending key sort == descending score, ascending index tiebreak
            unsigned long long key =
                ((unsigned long long)__float_as_uint(best) << 32) |
                (unsigned long long)(0xFFFFFFFFu - (unsigned)i);
            g_cand[pos] = key;
        }
    }
}

// ---------------------------------------------------------------------------
// Single block, 1024 threads: histogram suffix-scan to find threshold bucket,
// gather survivors (~300-400), bitonic sort, write exact sorted top-300.
__global__ void k_select() {
    __shared__ int sh[NBUCK];
    __shared__ unsigned long long keys[SORT_N];
    __shared__ int s_B, s_sel;
    int t = threadIdx.x;

    sh[t] = g_hist[t];
    __syncthreads();
    // suffix sum: sh[t] = sum_{b>=t} hist[b]
    for (int off = 1; off < NBUCK; off <<= 1) {
        int v = sh[t];
        int a = (t + off < NBUCK) ? sh[t + off] : 0;
        __syncthreads();
        sh[t] = v + a;
        __syncthreads();
    }
    int n_stored = min(g_cand_cnt, CAND_CAP);
    int total = sh[0];
    int target = min(K_DETS, min(total, n_stored));
    if (t == 0) { s_sel = 0; s_B = 0; }
    __syncthreads();
    if (target > 0) {
        if (sh[t] >= target && (t == NBUCK - 1 || sh[t + 1] < target)) s_B = t;
    }
    __syncthreads();
    int B = s_B;

    for (int i = t; i < SORT_N; i += blockDim.x) keys[i] = 0ull;
    __syncthreads();

    if (target > 0) {
        for (int i = t; i < n_stored; i += blockDim.x) {
            unsigned long long key = g_cand[i];
            float s = __uint_as_float((unsigned)(key >> 32));
            int b = (int)(s * 170.0f);
            b = max(0, min(NBUCK - 1, b));
            if (b >= B) {
                int p = atomicAdd(&s_sel, 1);
                if (p < SORT_N) keys[p] = key;
            }
        }
    }
    __syncthreads();

    // bitonic sort, descending
    for (int k = 2; k <= SORT_N; k <<= 1) {
        for (int j = k >> 1; j > 0; j >>= 1) {
            for (int idx = t; idx < SORT_N; idx += blockDim.x) {
                int l = idx ^ j;
                if (l > idx) {
                    unsigned long long a = keys[idx], b2 = keys[l];
                    bool up = ((idx & k) == 0);
                    if ((a < b2) == up) { keys[idx] = b2; keys[l] = a; }
                }
            }
            __syncthreads();
        }
    }

    if (t < K_DETS) {
        unsigned long long key = keys[t];
        if (t < target && key != 0ull) {
            g_top_idx[t]   = (int)(0xFFFFFFFFu - (unsigned)(key & 0xFFFFFFFFull));
            g_top_score[t] = __uint_as_float((unsigned)(key >> 32));
        } else {
            g_top_idx[t]   = -1;
            g_top_score[t] = 0.0f;
        }
    }
}

// ---------------------------------------------------------------------------
// Single block greedy NMS + scalar-output writes.
__global__ void k_nms(const float* __restrict__ raw, float* __restrict__ out) {
    __shared__ float bx1[K_DETS], by1[K_DETS], bx2[K_DETS], by2[K_DETS], bar[K_DETS];
    __shared__ int kp[K_DETS];
    int t = threadIdx.x;

    if (t < K_DETS) {
        int idx = g_top_idx[t];
        float x1 = 0.f, y1 = 0.f, x2 = 0.f, y2 = 0.f;
        if (idx >= 0) {
            float cx = raw[idx];
            float cy = raw[N_ANCHS + idx];
            float w  = raw[2 * N_ANCHS + idx];
            float h  = raw[3 * N_ANCHS + idx];
            x1 = cx - w * 0.5f; y1 = cy - h * 0.5f;
            x2 = cx + w * 0.5f; y2 = cy + h * 0.5f;
        }
        bx1[t] = x1; by1[t] = y1; bx2[t] = x2; by2[t] = y2;
        bar[t] = (x2 - x1) * (y2 - y1);
        kp[t] = (idx >= 0) ? 1 : 0;
    }
    for (int i = 0; i < K_DETS - 1; i++) {
        __syncthreads();
        if (t > i && t < K_DETS && kp[t] && kp[i]) {
            float lx = fmaxf(bx1[i], bx1[t]);
            float ly = fmaxf(by1[i], by1[t]);
            float rx = fminf(bx2[i], bx2[t]);
            float ry = fminf(by2[i], by2[t]);
            float iw = fmaxf(rx - lx, 0.0f);
            float ih = fmaxf(ry - ly, 0.0f);
            float inter = iw * ih;
            float uni = bar[i] + bar[t] - inter;
            float iou = inter / fmaxf(uni, 1e-9f);
            if (iou > 0.45f) kp[t] = 0;
        }
    }
    __syncthreads();
    if (t < K_DETS) {
        int k = kp[t];
        float fx1 = k ? bx1[t] : 0.f, fy1 = k ? by1[t] : 0.f;
        float fx2 = k ? bx2[t] : 0.f, fy2 = k ? by2[t] : 0.f;
        out[OFF_BOXES + 4 * t + 0] = fx1;
        out[OFF_BOXES + 4 * t + 1] = fy1;
        out[OFF_BOXES + 4 * t + 2] = fx2;
        out[OFF_BOXES + 4 * t + 3] = fy2;
        out[OFF_SCORES + t] = k ? g_top_score[t] : 0.0f;
        int cv = 0;
        int idx = g_top_idx[t];
        if (k && idx >= 0) cv = (int)g_cls[idx] + 1;
        out[OFF_CLASSES + t] = (float)cv;
        out[OFF_KEEP + t]    = k ? 1.0f : 0.0f;
        g_fbox[t] = make_float4(fx1, fy1, fx2, fy2);
        g_keep[t] = k;
    }
}

// ---------------------------------------------------------------------------
// Crop 0: full-image bilinear resize (== ROI with box (0,0,1280,1280)).
// Crops 1..300: ROI-align on final boxes; non-keep -> 0 pre-normalization.
__global__ void k_crops(const float* __restrict__ img, float* __restrict__ out) {
    int t = blockIdx.x * blockDim.x + threadIdx.x;
    if (t >= CROP_ELEMS) return;
    int b = blockIdx.y;

    float x1, y1, x2, y2; int kpF;
    if (b == 0) {
        x1 = 0.f; y1 = 0.f; x2 = (float)IMG_W; y2 = (float)IMG_W; kpF = 1;
    } else {
        kpF = g_keep[b - 1];
        float4 bb = g_fbox[b - 1];
        x1 = bb.x; y1 = bb.y; x2 = bb.z; y2 = bb.w;
    }

    int c   = t / CH_ELEMS;
    int rem = t - c * CH_ELEMS;
    int yo  = rem / OUTSZ;
    int xo  = rem - yo * OUTSZ;

    float val = 0.0f;
    if (kpF) {
        const float inv = 1.0f / (float)OUTSZ;
        float gx = ((float)xo + 0.5f) * inv;
        float gy = ((float)yo + 0.5f) * inv;
        float xs = x1 - 0.5f + gx * (x2 - x1);
        float ys = y1 - 0.5f + gy * (y2 - y1);
        if (xs >= -1.0f && xs <= (float)IMG_W && ys >= -1.0f && ys <= (float)IMG_W) {
            float xc = fminf(fmaxf(xs, 0.0f), (float)(IMG_W - 1));
            float yc = fminf(fmaxf(ys, 0.0f), (float)(IMG_W - 1));
            int x0 = (int)floorf(xc);
            int y0 = (int)floorf(yc);
            int x1i = min(x0 + 1, IMG_W - 1);
            int y1i = min(y0 + 1, IMG_W - 1);
            float lx = xc - (float)x0;
            float ly = yc - (float)y0;
            const float* p = img + c * (IMG_W * IMG_W);
            float v00 = p[y0 * IMG_W + x0];
            float v01 = p[y0 * IMG_W + x1i];
            float v10 = p[y1i * IMG_W + x0];
            float v11 = p[y1i * IMG_W + x1i];
            float top = v00 * (1.0f - lx) + v01 * lx;
            float bot = v10 * (1.0f - lx) + v11 * lx;
            val = top * (1.0f - ly) + bot * ly;
        }
    }
    out[OFF_CROPS + b * CROP_ELEMS + t] = (val - c_mean[c]) * c_istd[c];
}

// ---------------------------------------------------------------------------
extern "C" void kernel_launch(void* const* d_in, const int* in_sizes, int n_in,
                              void* d_out, int out_size) {
    const float* raw = (const float*)d_in[0];   // (1,85,100800)
    const float* img = (const float*)d_in[1];   // (1,3,1280,1280)
    float* out = (float*)d_out;

    k_init<<<1, 1024>>>();
    k_score<<<(N_ANCHS + 255) / 256, 256>>>(raw);
    k_select<<<1, 1024>>>();
    k_nms<<<1, 512>>>(raw, out);
    dim3 g((CROP_ELEMS + 255) / 256, 301);
    k_crops<<<g, 256>>>(img, out);
}

// round 2
// speedup vs baseline: 1.4768x; 1.4768x over previous
#include <cuda_runtime.h>

#define N_ANCHS   100800
#define NCLS      80
#define IMG_W     1280
#define K_DETS    300
#define OUTSZ     224
#define CAND_CAP  16384
#define SORT_N    2048
#define NBUCK     1024
#define CH_ELEMS  (OUTSZ*OUTSZ)        // 50176
#define CROP_ELEMS (3*CH_ELEMS)        // 150528
#define NMS_WORDS 10                   // ceil(300/32)

// Output layout (flattened tuple, fp32):
//   [0,1200)            final_boxes  (300,4)
//   [1200,1500)         final_scores (300)
//   [1500,1800)         final_classes(300)
//   [1800,45310728)     all_crops    (301,3,224,224)
//   [45310728,45311028) keep         (300)
#define OFF_BOXES   0
#define OFF_SCORES  1200
#define OFF_CLASSES 1500
#define OFF_CROPS   1800
#define OFF_KEEP    45310728

__device__ unsigned long long g_cand[CAND_CAP];
__device__ int   g_cand_cnt;
__device__ int   g_hist[NBUCK];
__device__ unsigned char g_cls[N_ANCHS];
__device__ int   g_top_idx[K_DETS];
__device__ float g_top_score[K_DETS];
__device__ float4 g_fbox[K_DETS];
__device__ int   g_keep[K_DETS];

__constant__ float c_mean[3] = {0.485f, 0.456f, 0.406f};
__constant__ float c_istd[3] = {1.0f/0.229f, 1.0f/0.224f, 1.0f/0.225f};

// ---------------------------------------------------------------------------
__global__ void k_init() {
    int t = threadIdx.x;
    if (t == 0) g_cand_cnt = 0;
    for (int b = t; b < NBUCK; b += blockDim.x) g_hist[b] = 0;
}

// ---------------------------------------------------------------------------
// 4 anchors per thread, float4 loads over the 80 class-logit channels.
__global__ void k_score(const float* __restrict__ raw) {
    int q = blockIdx.x * blockDim.x + threadIdx.x;   // 0..25199
    if (q >= N_ANCHS / 4) return;
    int i0 = q * 4;
    const float4* lg = (const float4*)(raw + 5 * N_ANCHS);

    float4 v0 = lg[q];
    float best[4] = {v0.x, v0.y, v0.z, v0.w};
    int   bc[4]   = {0, 0, 0, 0};
    #pragma unroll 4
    for (int c = 1; c < NCLS; c++) {
        float4 v = lg[c * (N_ANCHS / 4) + q];
        if (v.x > best[0]) { best[0] = v.x; bc[0] = c; }
        if (v.y > best[1]) { best[1] = v.y; bc[1] = c; }
        if (v.z > best[2]) { best[2] = v.z; bc[2] = c; }
        if (v.w > best[3]) { best[3] = v.w; bc[3] = c; }
    }
    #pragma unroll
    for (int k = 0; k < 4; k++) {
        int i = i0 + k;
        g_cls[i] = (unsigned char)bc[k];
        int cls = bc[k] + 1;
        bool allowed = (cls==1)|(cls==2)|(cls==3)|(cls==4)|(cls==6)|(cls==8)|
                       (cls==17)|(cls==18)|(cls==44);
        if (allowed && best[k] > 0.1f) {
            int b = (int)(best[k] * 170.0f);
            b = max(0, min(NBUCK - 1, b));
            atomicAdd(&g_hist[b], 1);
            int pos = atomicAdd(&g_cand_cnt, 1);
            if (pos < CAND_CAP) {
                unsigned long long key =
                    ((unsigned long long)__float_as_uint(best[k]) << 32) |
                    (unsigned long long)(0xFFFFFFFFu - (unsigned)i);
                g_cand[pos] = key;
            }
        }
    }
}

// ---------------------------------------------------------------------------
// Single block, 1024 threads: histogram suffix-scan -> threshold bucket,
// gather survivors, bitonic sort 2048, emit exact sorted top-300.
__global__ void k_select() {
    __shared__ int sh[NBUCK];
    __shared__ unsigned long long keys[SORT_N];
    __shared__ int s_B, s_sel;
    int t = threadIdx.x;

    sh[t] = g_hist[t];
    __syncthreads();
    for (int off = 1; off < NBUCK; off <<= 1) {
        int v = sh[t];
        int a = (t + off < NBUCK) ? sh[t + off] : 0;
        __syncthreads();
        sh[t] = v + a;
        __syncthreads();
    }
    int n_stored = min(g_cand_cnt, CAND_CAP);
    int total = sh[0];
    int target = min(K_DETS, min(total, n_stored));
    if (t == 0) { s_sel = 0; s_B = 0; }
    __syncthreads();
    if (target > 0) {
        if (sh[t] >= target && (t == NBUCK - 1 || sh[t + 1] < target)) s_B = t;
    }
    __syncthreads();
    int B = s_B;

    for (int i = t; i < SORT_N; i += blockDim.x) keys[i] = 0ull;
    __syncthreads();

    if (target > 0) {
        for (int i = t; i < n_stored; i += blockDim.x) {
            unsigned long long key = g_cand[i];
            float s = __uint_as_float((unsigned)(key >> 32));
            int b = (int)(s * 170.0f);
            b = max(0, min(NBUCK - 1, b));
            if (b >= B) {
                int p = atomicAdd(&s_sel, 1);
                if (p < SORT_N) keys[p] = key;
            }
        }
    }
    __syncthreads();

    for (int k = 2; k <= SORT_N; k <<= 1) {
        for (int j = k >> 1; j > 0; j >>= 1) {
            for (int idx = t; idx < SORT_N; idx += blockDim.x) {
                int l = idx ^ j;
                if (l > idx) {
                    unsigned long long a = keys[idx], b2 = keys[l];
                    bool up = ((idx & k) == 0);
                    if ((a < b2) == up) { keys[idx] = b2; keys[l] = a; }
                }
            }
            __syncthreads();
        }
    }

    if (t < K_DETS) {
        unsigned long long key = keys[t];
        if (t < target && key != 0ull) {
            g_top_idx[t]   = (int)(0xFFFFFFFFu - (unsigned)(key & 0xFFFFFFFFull));
            g_top_score[t] = __uint_as_float((unsigned)(key >> 32));
        } else {
            g_top_idx[t]   = -1;
            g_top_score[t] = 0.0f;
        }
    }
}

// ---------------------------------------------------------------------------
// Bitmask NMS: parallel 300x300 IOU -> suppression bitmask, then single-warp
// greedy scan with register-resident removal words.
__global__ void k_nms(const float* __restrict__ raw, float* __restrict__ out) {
    __shared__ float bx1[K_DETS], by1[K_DETS], bx2[K_DETS], by2[K_DETS], bar[K_DETS];
    __shared__ unsigned mask[K_DETS][NMS_WORDS];
    __shared__ unsigned char valid[K_DETS];
    __shared__ unsigned char final_kp[K_DETS];
    int t = threadIdx.x;   // 512

    if (t < K_DETS) {
        int idx = g_top_idx[t];
        float x1 = 0.f, y1 = 0.f, x2 = 0.f, y2 = 0.f;
        if (idx >= 0) {
            float cx = raw[idx];
            float cy = raw[N_ANCHS + idx];
            float w  = raw[2 * N_ANCHS + idx];
            float h  = raw[3 * N_ANCHS + idx];
            x1 = cx - w * 0.5f; y1 = cy - h * 0.5f;
            x2 = cx + w * 0.5f; y2 = cy + h * 0.5f;
        }
        bx1[t] = x1; by1[t] = y1; bx2[t] = x2; by2[t] = y2;
        bar[t] = (x2 - x1) * (y2 - y1);
        valid[t] = (idx >= 0) ? 1 : 0;
    }
    __syncthreads();

    // Build suppression bitmask: task = i*NMS_WORDS + w
    for (int task = t; task < K_DETS * NMS_WORDS; task += blockDim.x) {
        int i = task / NMS_WORDS;
        int w = task - i * NMS_WORDS;
        float ix1 = bx1[i], iy1 = by1[i], ix2 = bx2[i], iy2 = by2[i], ia = bar[i];
        unsigned m = 0;
        int jbase = w << 5;
        #pragma unroll 8
        for (int k = 0; k < 32; k++) {
            int j = jbase + k;
            if (j < K_DETS && j > i) {
                float lx = fmaxf(ix1, bx1[j]);
                float ly = fmaxf(iy1, by1[j]);
                float rx = fminf(ix2, bx2[j]);
                float ry = fminf(iy2, by2[j]);
                float iw = fmaxf(rx - lx, 0.0f);
                float ih = fmaxf(ry - ly, 0.0f);
                float inter = iw * ih;
                float uni = ia + bar[j] - inter;
                float iou = inter / fmaxf(uni, 1e-9f);
                if (iou > 0.45f) m |= (1u << k);
            }
        }
        mask[i][w] = m;
    }
    __syncthreads();

    // Greedy scan by warp 0; lane w (<NMS_WORDS) owns removal word w.
    if (t < 32) {
        unsigned rm = 0;
        for (int i = 0; i < K_DETS; i++) {
            int w = i >> 5, b = i & 31;
            unsigned word = __shfl_sync(0xffffffffu, rm, w);
            bool alive = valid[i] && !((word >> b) & 1u);
            if (t == 0) final_kp[i] = alive ? 1 : 0;
            if (alive && t < NMS_WORDS) rm |= mask[i][t];
        }
    }
    __syncthreads();

    if (t < K_DETS) {
        int k = final_kp[t];
        float fx1 = k ? bx1[t] : 0.f, fy1 = k ? by1[t] : 0.f;
        float fx2 = k ? bx2[t] : 0.f, fy2 = k ? by2[t] : 0.f;
        out[OFF_BOXES + 4 * t + 0] = fx1;
        out[OFF_BOXES + 4 * t + 1] = fy1;
        out[OFF_BOXES + 4 * t + 2] = fx2;
        out[OFF_BOXES + 4 * t + 3] = fy2;
        out[OFF_SCORES + t] = k ? g_top_score[t] : 0.0f;
        int cv = 0;
        int idx = g_top_idx[t];
        if (k && idx >= 0) cv = (int)g_cls[idx] + 1;
        out[OFF_CLASSES + t] = (float)cv;
        out[OFF_KEEP + t]    = k ? 1.0f : 0.0f;
        g_fbox[t] = make_float4(fx1, fy1, fx2, fy2);
        g_keep[t] = k;
    }
}

// ---------------------------------------------------------------------------
// Crops: 4 output pixels per thread (same row), float4 store.
// Crop 0 = full-image bilinear resize (ROI with box (0,0,1280,1280)).
__global__ void k_crops(const float* __restrict__ img, float* __restrict__ out) {
    int q = blockIdx.x * blockDim.x + threadIdx.x;   // 0..37631
    if (q >= CROP_ELEMS / 4) return;
    int b = blockIdx.y;
    int pix = q * 4;
    int c   = pix / CH_ELEMS;
    int rem = pix - c * CH_ELEMS;
    int yo  = rem / OUTSZ;
    int xo  = rem - yo * OUTSZ;

    float mean = c_mean[c], istd = c_istd[c];

    float x1, y1, x2, y2; int kpF;
    if (b == 0) {
        x1 = 0.f; y1 = 0.f; x2 = (float)IMG_W; y2 = (float)IMG_W; kpF = 1;
    } else {
        kpF = g_keep[b - 1];
        float4 bb = g_fbox[b - 1];
        x1 = bb.x; y1 = bb.y; x2 = bb.z; y2 = bb.w;
    }

    float4 r;
    if (!kpF) {
        float z = -mean * istd;
        r = make_float4(z, z, z, z);
    } else {
        const float inv = 1.0f / (float)OUTSZ;
        float dy = y2 - y1, dx = x2 - x1;
        float gy = ((float)yo + 0.5f) * inv;
        float ys = y1 - 0.5f + gy * dy;
        bool  vy = (ys >= -1.0f) && (ys <= (float)IMG_W);
        float yc = fminf(fmaxf(ys, 0.0f), (float)(IMG_W - 1));
        int   y0 = (int)floorf(yc);
        int   y1i = min(y0 + 1, IMG_W - 1);
        float ly = yc - (float)y0;
        const float* p0 = img + c * (IMG_W * IMG_W) + y0  * IMG_W;
        const float* p1 = img + c * (IMG_W * IMG_W) + y1i * IMG_W;

        float v[4];
        #pragma unroll
        for (int k = 0; k < 4; k++) {
            float gx = ((float)(xo + k) + 0.5f) * inv;
            float xs = x1 - 0.5f + gx * dx;
            float val = 0.0f;
            if (vy && xs >= -1.0f && xs <= (float)IMG_W) {
                float xc = fminf(fmaxf(xs, 0.0f), (float)(IMG_W - 1));
                int x0 = (int)floorf(xc);
                int x1i = min(x0 + 1, IMG_W - 1);
                float lx = xc - (float)x0;
                float v00 = p0[x0];
                float v01 = p0[x1i];
                float v10 = p1[x0];
                float v11 = p1[x1i];
                float top = v00 * (1.0f - lx) + v01 * lx;
                float bot = v10 * (1.0f - lx) + v11 * lx;
                val = top * (1.0f - ly) + bot * ly;
            }
            v[k] = (val - mean) * istd;
        }
        r = make_float4(v[0], v[1], v[2], v[3]);
    }
    ((float4*)(out + OFF_CROPS + (size_t)b * CROP_ELEMS))[q] = r;
}

// ---------------------------------------------------------------------------
extern "C" void kernel_launch(void* const* d_in, const int* in_sizes, int n_in,
                              void* d_out, int out_size) {
    const float* raw = (const float*)d_in[0];   // (1,85,100800)
    const float* img = (const float*)d_in[1];   // (1,3,1280,1280)
    float* out = (float*)d_out;

    k_init<<<1, 1024>>>();
    k_score<<<(N_ANCHS / 4 + 255) / 256, 256>>>(raw);
    k_select<<<1, 1024>>>();
    k_nms<<<1, 512>>>(raw, out);
    dim3 g((CROP_ELEMS / 4 + 255) / 256, 301);
    k_crops<<<g, 256>>>(img, out);
}

// round 3
// speedup vs baseline: 1.9667x; 1.3317x over previous
#include <cuda_runtime.h>

#define N_ANCHS   100800
#define NCLS      80
#define IMG_W     1280
#define K_DETS    300
#define CAND_CAP  16384
#define SORT_N    2048
#define NBUCK     1024
#define OUTSZ     224
#define CH_ELEMS  (OUTSZ*OUTSZ)        // 50176
#define CROP_ELEMS (3*CH_ELEMS)        // 150528
#define NMS_WORDS 10                   // ceil(300/32)

// Output layout (flattened tuple, fp32):
//   [0,1200)            final_boxes  (300,4)
//   [1200,1500)         final_scores (300)
//   [1500,1800)         final_classes(300)
//   [1800,45310728)     all_crops    (301,3,224,224)
//   [45310728,45311028) keep         (300)
#define OFF_BOXES   0
#define OFF_SCORES  1200
#define OFF_CLASSES 1500
#define OFF_CROPS   1800
#define OFF_KEEP    45310728

__device__ unsigned long long g_cand[CAND_CAP];
__device__ int      g_cand_cnt;          // zero-init; re-zeroed by k_greedy
__device__ int      g_hist[NBUCK];       // zero-init; re-zeroed by k_greedy
__device__ unsigned char g_cls[N_ANCHS];
__device__ int      g_top_idx[K_DETS];
__device__ float    g_top_score[K_DETS];
__device__ float4   g_bbx[K_DETS];
__device__ float    g_area[K_DETS];
__device__ int      g_validArr[K_DETS];
__device__ unsigned g_mask[K_DETS * NMS_WORDS];
__device__ float4   g_fbox[K_DETS];
__device__ int      g_keep[K_DETS];

__constant__ float c_mean[3] = {0.485f, 0.456f, 0.406f};
__constant__ float c_istd[3] = {1.0f/0.229f, 1.0f/0.224f, 1.0f/0.225f};

// ---------------------------------------------------------------------------
// 4 anchors per thread, float4 loads over the 80 class-logit channels.
__global__ void k_score(const float* __restrict__ raw) {
    int q = blockIdx.x * blockDim.x + threadIdx.x;   // 0..25199
    if (q >= N_ANCHS / 4) return;
    int i0 = q * 4;
    const float4* lg = (const float4*)(raw + 5 * N_ANCHS);

    float4 v0 = lg[q];
    float best[4] = {v0.x, v0.y, v0.z, v0.w};
    int   bc[4]   = {0, 0, 0, 0};
    #pragma unroll 4
    for (int c = 1; c < NCLS; c++) {
        float4 v = lg[c * (N_ANCHS / 4) + q];
        if (v.x > best[0]) { best[0] = v.x; bc[0] = c; }
        if (v.y > best[1]) { best[1] = v.y; bc[1] = c; }
        if (v.z > best[2]) { best[2] = v.z; bc[2] = c; }
        if (v.w > best[3]) { best[3] = v.w; bc[3] = c; }
    }
    #pragma unroll
    for (int k = 0; k < 4; k++) {
        int i = i0 + k;
        g_cls[i] = (unsigned char)bc[k];
        int cls = bc[k] + 1;
        bool allowed = (cls==1)|(cls==2)|(cls==3)|(cls==4)|(cls==6)|(cls==8)|
                       (cls==17)|(cls==18)|(cls==44);
        if (allowed && best[k] > 0.1f) {
            int b = (int)(best[k] * 170.0f);
            b = max(0, min(NBUCK - 1, b));
            atomicAdd(&g_hist[b], 1);
            int pos = atomicAdd(&g_cand_cnt, 1);
            if (pos < CAND_CAP) {
                unsigned long long key =
                    ((unsigned long long)__float_as_uint(best[k]) << 32) |
                    (unsigned long long)(0xFFFFFFFFu - (unsigned)i);
                g_cand[pos] = key;
            }
        }
    }
}

// ---------------------------------------------------------------------------
// Single block, 1024 threads: histogram suffix-scan -> threshold bucket,
// gather survivors, bitonic sort, emit exact sorted top-300, precompute boxes.
__global__ void k_select(const float* __restrict__ raw) {
    __shared__ int sh[NBUCK];
    __shared__ unsigned long long keys[SORT_N];
    __shared__ int s_B, s_sel;
    int t = threadIdx.x;

    sh[t] = g_hist[t];
    __syncthreads();
    for (int off = 1; off < NBUCK; off <<= 1) {
        int v = sh[t];
        int a = (t + off < NBUCK) ? sh[t + off] : 0;
        __syncthreads();
        sh[t] = v + a;
        __syncthreads();
    }
    int n_stored = min(g_cand_cnt, CAND_CAP);
    int total = sh[0];
    int target = min(K_DETS, min(total, n_stored));
    if (t == 0) { s_sel = 0; s_B = 0; }
    __syncthreads();
    if (target > 0) {
        if (sh[t] >= target && (t == NBUCK - 1 || sh[t + 1] < target)) s_B = t;
    }
    __syncthreads();
    int B = s_B;

    for (int i = t; i < SORT_N; i += blockDim.x) keys[i] = 0ull;
    __syncthreads();

    if (target > 0) {
        for (int i = t; i < n_stored; i += blockDim.x) {
            unsigned long long key = g_cand[i];
            float s = __uint_as_float((unsigned)(key >> 32));
            int b = (int)(s * 170.0f);
            b = max(0, min(NBUCK - 1, b));
            if (b >= B) {
                int p = atomicAdd(&s_sel, 1);
                if (p < SORT_N) keys[p] = key;
            }
        }
    }
    __syncthreads();

    for (int k = 2; k <= SORT_N; k <<= 1) {
        for (int j = k >> 1; j > 0; j >>= 1) {
            for (int idx = t; idx < SORT_N; idx += blockDim.x) {
                int l = idx ^ j;
                if (l > idx) {
                    unsigned long long a = keys[idx], b2 = keys[l];
                    bool up = ((idx & k) == 0);
                    if ((a < b2) == up) { keys[idx] = b2; keys[l] = a; }
                }
            }
            __syncthreads();
        }
    }

    if (t < K_DETS) {
        unsigned long long key = keys[t];
        int idx = -1;
        float sc = 0.0f;
        if (t < target && key != 0ull) {
            idx = (int)(0xFFFFFFFFu - (unsigned)(key & 0xFFFFFFFFull));
            sc  = __uint_as_float((unsigned)(key >> 32));
        }
        g_top_idx[t]   = idx;
        g_top_score[t] = sc;
        float x1 = 0.f, y1 = 0.f, x2 = 0.f, y2 = 0.f;
        if (idx >= 0) {
            float cx = raw[idx];
            float cy = raw[N_ANCHS + idx];
            float w  = raw[2 * N_ANCHS + idx];
            float h  = raw[3 * N_ANCHS + idx];
            x1 = cx - w * 0.5f; y1 = cy - h * 0.5f;
            x2 = cx + w * 0.5f; y2 = cy + h * 0.5f;
        }
        g_bbx[t]  = make_float4(x1, y1, x2, y2);
        g_area[t] = (x2 - x1) * (y2 - y1);
        g_validArr[t] = (idx >= 0) ? 1 : 0;
    }
}

// ---------------------------------------------------------------------------
// One warp per box i; lane = j. Coalesced loads, ballot -> mask word.
__global__ void k_mask() {
    int gw = (blockIdx.x * blockDim.x + threadIdx.x) >> 5;
    int lane = threadIdx.x & 31;
    if (gw >= K_DETS) return;
    float4 bi = g_bbx[gw];
    float  ia = g_area[gw];
    #pragma unroll
    for (int w = 0; w < NMS_WORDS; w++) {
        int j = (w << 5) + lane;
        bool sup = false;
        if (j < K_DETS && j > gw) {
            float4 bj = g_bbx[j];
            float lx = fmaxf(bi.x, bj.x);
            float ly = fmaxf(bi.y, bj.y);
            float rx = fminf(bi.z, bj.z);
            float ry = fminf(bi.w, bj.w);
            float iw = fmaxf(rx - lx, 0.0f);
            float ih = fmaxf(ry - ly, 0.0f);
            float inter = iw * ih;
            float uni = ia + g_area[j] - inter;
            sup = (inter / fmaxf(uni, 1e-9f)) > 0.45f;
        }
        unsigned m = __ballot_sync(0xffffffffu, sup);
        if (lane == 0) g_mask[gw * NMS_WORDS + w] = m;
    }
}

// ---------------------------------------------------------------------------
// Single block: smem-staged greedy scan (warp 0), output writes, and
// state re-zeroing for the next graph replay.
__global__ void k_greedy(float* __restrict__ out) {
    __shared__ unsigned s_mask[K_DETS * NMS_WORDS];
    __shared__ unsigned char s_kp[K_DETS];
    int t = threadIdx.x;   // 512

    // Stage mask into smem (coalesced) + re-zero persistent state.
    for (int i = t; i < K_DETS * NMS_WORDS; i += blockDim.x) s_mask[i] = g_mask[i];
    for (int b = t; b < NBUCK; b += blockDim.x) g_hist[b] = 0;
    if (t == 0) g_cand_cnt = 0;
    __syncthreads();

    if (t < 32) {
        // Pre-remove invalid boxes: lane w holds removal word w.
        unsigned rm = 0;
        #pragma unroll
        for (int w = 0; w < NMS_WORDS; w++) {
            int j = (w << 5) + t;
            bool inv = (j < K_DETS) ? (g_validArr[j] == 0) : false;
            unsigned bword = __ballot_sync(0xffffffffu, inv);
            if (t == w) rm = bword;
        }
        unsigned cur = (t < NMS_WORDS) ? s_mask[t] : 0;
        for (int i = 0; i < K_DETS; i++) {
            unsigned nxt = (t < NMS_WORDS && i + 1 < K_DETS)
                           ? s_mask[(i + 1) * NMS_WORDS + t] : 0;
            unsigned word = __shfl_sync(0xffffffffu, rm, i >> 5);
            bool alive = !((word >> (i & 31)) & 1u);
            if (alive) rm |= cur;
            if (t == 0) s_kp[i] = alive ? 1 : 0;
            cur = nxt;
        }
    }
    __syncthreads();

    if (t < K_DETS) {
        int k = s_kp[t];
        float4 bb = g_bbx[t];
        float fx1 = k ? bb.x : 0.f, fy1 = k ? bb.y : 0.f;
        float fx2 = k ? bb.z : 0.f, fy2 = k ? bb.w : 0.f;
        out[OFF_BOXES + 4 * t + 0] = fx1;
        out[OFF_BOXES + 4 * t + 1] = fy1;
        out[OFF_BOXES + 4 * t + 2] = fx2;
        out[OFF_BOXES + 4 * t + 3] = fy2;
        out[OFF_SCORES + t] = k ? g_top_score[t] : 0.0f;
        int cv = 0;
        int idx = g_top_idx[t];
        if (k && idx >= 0) cv = (int)g_cls[idx] + 1;
        out[OFF_CLASSES + t] = (float)cv;
        out[OFF_KEEP + t]    = k ? 1.0f : 0.0f;
        g_fbox[t] = make_float4(fx1, fy1, fx2, fy2);
        g_keep[t] = k;
    }
}

// ---------------------------------------------------------------------------
// Crops: 4 output pixels per thread (same row), float4 store.
// Crop 0 = full-image bilinear resize (ROI with box (0,0,1280,1280)).
__global__ void k_crops(const float* __restrict__ img, float* __restrict__ out) {
    int q = blockIdx.x * blockDim.x + threadIdx.x;   // 0..37631
    if (q >= CROP_ELEMS / 4) return;
    int b = blockIdx.y;
    int pix = q * 4;
    int c   = pix / CH_ELEMS;
    int rem = pix - c * CH_ELEMS;
    int yo  = rem / OUTSZ;
    int xo  = rem - yo * OUTSZ;

    float mean = c_mean[c], istd = c_istd[c];

    float x1, y1, x2, y2; int kpF;
    if (b == 0) {
        x1 = 0.f; y1 = 0.f; x2 = (float)IMG_W; y2 = (float)IMG_W; kpF = 1;
    } else {
        kpF = g_keep[b - 1];
        float4 bb = g_fbox[b - 1];
        x1 = bb.x; y1 = bb.y; x2 = bb.z; y2 = bb.w;
    }

    float4 r;
    if (!kpF) {
        float z = -mean * istd;
        r = make_float4(z, z, z, z);
    } else {
        const float inv = 1.0f / (float)OUTSZ;
        float dy = y2 - y1, dx = x2 - x1;
        float gy = ((float)yo + 0.5f) * inv;
        float ys = y1 - 0.5f + gy * dy;
        bool  vy = (ys >= -1.0f) && (ys <= (float)IMG_W);
        float yc = fminf(fmaxf(ys, 0.0f), (float)(IMG_W - 1));
        int   y0 = (int)floorf(yc);
        int   y1i = min(y0 + 1, IMG_W - 1);
        float ly = yc - (float)y0;
        const float* p0 = img + c * (IMG_W * IMG_W) + y0  * IMG_W;
        const float* p1 = img + c * (IMG_W * IMG_W) + y1i * IMG_W;

        float v[4];
        #pragma unroll
        for (int k = 0; k < 4; k++) {
            float gx = ((float)(xo + k) + 0.5f) * inv;
            float xs = x1 - 0.5f + gx * dx;
            float val = 0.0f;
            if (vy && xs >= -1.0f && xs <= (float)IMG_W) {
                float xc = fminf(fmaxf(xs, 0.0f), (float)(IMG_W - 1));
                int x0 = (int)floorf(xc);
                int x1i = min(x0 + 1, IMG_W - 1);
                float lx = xc - (float)x0;
                float v00 = p0[x0];
                float v01 = p0[x1i];
                float v10 = p1[x0];
                float v11 = p1[x1i];
                float top = v00 * (1.0f - lx) + v01 * lx;
                float bot = v10 * (1.0f - lx) + v11 * lx;
                val = top * (1.0f - ly) + bot * ly;
            }
            v[k] = (val - mean) * istd;
        }
        r = make_float4(v[0], v[1], v[2], v[3]);
    }
    ((float4*)(out + OFF_CROPS + (size_t)b * CROP_ELEMS))[q] = r;
}

// ---------------------------------------------------------------------------
extern "C" void kernel_launch(void* const* d_in, const int* in_sizes, int n_in,
                              void* d_out, int out_size) {
    const float* raw = (const float*)d_in[0];   // (1,85,100800)
    const float* img = (const float*)d_in[1];   // (1,3,1280,1280)
    float* out = (float*)d_out;

    k_score<<<(N_ANCHS / 4 + 255) / 256, 256>>>(raw);
    k_select<<<1, 1024>>>(raw);
    k_mask<<<(K_DETS * 32 + 255) / 256, 256>>>();
    k_greedy<<<1, 512>>>(out);
    dim3 g((CROP_ELEMS / 4 + 255) / 256, 301);
    k_crops<<<g, 256>>>(img, out);
}

// round 4
// speedup vs baseline: 1.9943x; 1.0140x over previous
#include <cuda_runtime.h>

#define N_ANCHS   100800
#define NCLS      80
#define IMG_W     1280
#define K_DETS    300
#define CAND_CAP  16384
#define SORT_N    1024
#define NBUCK     1024
#define OUTSZ     224
#define CH_ELEMS  (OUTSZ*OUTSZ)        // 50176
#define CROP_ELEMS (3*CH_ELEMS)        // 150528
#define NMS_WORDS 10                   // ceil(300/32)

// Output layout (flattened tuple, fp32):
//   [0,1200)            final_boxes  (300,4)
//   [1200,1500)         final_scores (300)
//   [1500,1800)         final_classes(300)
//   [1800,45310728)     all_crops    (301,3,224,224)
//   [45310728,45311028) keep         (300)
#define OFF_BOXES   0
#define OFF_SCORES  1200
#define OFF_CLASSES 1500
#define OFF_CROPS   1800
#define OFF_KEEP    45310728

__device__ unsigned long long g_cand[CAND_CAP];
__device__ int      g_cand_cnt;          // zero-init; re-zeroed by k_select_nms
__device__ int      g_hist[NBUCK];       // zero-init; re-zeroed by k_select_nms
__device__ unsigned char g_cls[N_ANCHS];
__device__ float4   g_fbox[K_DETS];
__device__ int      g_keep[K_DETS];

__constant__ float c_mean[3] = {0.485f, 0.456f, 0.406f};
__constant__ float c_istd[3] = {1.0f/0.229f, 1.0f/0.224f, 1.0f/0.225f};

// ---------------------------------------------------------------------------
// 4 anchors per thread, float4 loads over the 80 class-logit channels.
__global__ void k_score(const float* __restrict__ raw) {
    int q = blockIdx.x * blockDim.x + threadIdx.x;   // 0..25199
    if (q >= N_ANCHS / 4) return;
    int i0 = q * 4;
    const float4* lg = (const float4*)(raw + 5 * N_ANCHS);

    float4 v0 = lg[q];
    float best[4] = {v0.x, v0.y, v0.z, v0.w};
    int   bc[4]   = {0, 0, 0, 0};
    #pragma unroll 4
    for (int c = 1; c < NCLS; c++) {
        float4 v = lg[c * (N_ANCHS / 4) + q];
        if (v.x > best[0]) { best[0] = v.x; bc[0] = c; }
        if (v.y > best[1]) { best[1] = v.y; bc[1] = c; }
        if (v.z > best[2]) { best[2] = v.z; bc[2] = c; }
        if (v.w > best[3]) { best[3] = v.w; bc[3] = c; }
    }
    #pragma unroll
    for (int k = 0; k < 4; k++) {
        int i = i0 + k;
        g_cls[i] = (unsigned char)bc[k];
        int cls = bc[k] + 1;
        bool allowed = (cls==1)|(cls==2)|(cls==3)|(cls==4)|(cls==6)|(cls==8)|
                       (cls==17)|(cls==18)|(cls==44);
        if (allowed && best[k] > 0.1f) {
            int b = (int)(best[k] * 170.0f);
            b = max(0, min(NBUCK - 1, b));
            atomicAdd(&g_hist[b], 1);
            int pos = atomicAdd(&g_cand_cnt, 1);
            if (pos < CAND_CAP) {
                unsigned long long key =
                    ((unsigned long long)__float_as_uint(best[k]) << 32) |
                    (unsigned long long)(0xFFFFFFFFu - (unsigned)i);
                g_cand[pos] = key;
            }
        }
    }
}

// ---------------------------------------------------------------------------
// Fused: top-K selection (histogram + bitonic sort) -> box decode -> NMS mask
// build -> greedy scan -> scalar outputs. One block, 1024 threads.
__global__ void k_select_nms(const float* __restrict__ raw, float* __restrict__ out) {
    __shared__ int sh[NBUCK];
    __shared__ unsigned long long keys[SORT_N];
    __shared__ float sx1[K_DETS], sy1[K_DETS], sx2[K_DETS], sy2[K_DETS], sar[K_DETS];
    __shared__ float sscore[K_DETS];
    __shared__ int   sidx[K_DETS];
    __shared__ unsigned char svalid[K_DETS];
    __shared__ unsigned s_mask[K_DETS * NMS_WORDS];
    __shared__ unsigned char s_kp[K_DETS];
    __shared__ int s_B, s_sel;
    int t = threadIdx.x;

    // --- Phase A: histogram suffix-scan -> threshold bucket ---
    sh[t] = g_hist[t];
    __syncthreads();
    for (int off = 1; off < NBUCK; off <<= 1) {
        int v = sh[t];
        int a = (t + off < NBUCK) ? sh[t + off] : 0;
        __syncthreads();
        sh[t] = v + a;
        __syncthreads();
    }
    int n_stored = min(g_cand_cnt, CAND_CAP);
    int total = sh[0];
    int target = min(K_DETS, min(total, n_stored));
    if (t == 0) { s_sel = 0; s_B = 0; }
    __syncthreads();
    if (target > 0) {
        if (sh[t] >= target && (t == NBUCK - 1 || sh[t + 1] < target)) s_B = t;
    }
    __syncthreads();
    int B = s_B;

    keys[t] = 0ull;
    __syncthreads();

    // --- Phase B: gather survivors ---
    if (target > 0) {
        for (int i = t; i < n_stored; i += blockDim.x) {
            unsigned long long key = g_cand[i];
            float s = __uint_as_float((unsigned)(key >> 32));
            int b = (int)(s * 170.0f);
            b = max(0, min(NBUCK - 1, b));
            if (b >= B) {
                int p = atomicAdd(&s_sel, 1);
                if (p < SORT_N) keys[p] = key;
            }
        }
    }
    __syncthreads();

    // --- Phase C: bitonic sort (descending), 1024 keys, 1024 threads ---
    for (int k = 2; k <= SORT_N; k <<= 1) {
        for (int j = k >> 1; j > 0; j >>= 1) {
            int l = t ^ j;
            if (l > t) {
                unsigned long long a = keys[t], b2 = keys[l];
                bool up = ((t & k) == 0);
                if ((a < b2) == up) { keys[t] = b2; keys[l] = a; }
            }
            __syncthreads();
        }
    }

    // --- Phase D: decode top-300 boxes into smem ---
    if (t < K_DETS) {
        unsigned long long key = keys[t];
        int idx = -1;
        float sc = 0.0f;
        if (t < target && key != 0ull) {
            idx = (int)(0xFFFFFFFFu - (unsigned)(key & 0xFFFFFFFFull));
            sc  = __uint_as_float((unsigned)(key >> 32));
        }
        sidx[t]   = idx;
        sscore[t] = sc;
        float x1 = 0.f, y1 = 0.f, x2 = 0.f, y2 = 0.f;
        if (idx >= 0) {
            float cx = raw[idx];
            float cy = raw[N_ANCHS + idx];
            float w  = raw[2 * N_ANCHS + idx];
            float h  = raw[3 * N_ANCHS + idx];
            x1 = cx - w * 0.5f; y1 = cy - h * 0.5f;
            x2 = cx + w * 0.5f; y2 = cy + h * 0.5f;
        }
        sx1[t] = x1; sy1[t] = y1; sx2[t] = x2; sy2[t] = y2;
        sar[t] = (x2 - x1) * (y2 - y1);
        svalid[t] = (idx >= 0) ? 1 : 0;
    }
    // Re-zero persistent state for the next graph replay (idle threads busy).
    g_hist[t] = 0;
    if (t == 0) g_cand_cnt = 0;
    __syncthreads();

    // --- Phase E: mask build. Warp w handles rows i = w, w+32, ... ---
    {
        int warp = t >> 5, lane = t & 31;
        for (int i = warp; i < K_DETS; i += 32) {
            float ix1 = sx1[i], iy1 = sy1[i], ix2 = sx2[i], iy2 = sy2[i], ia = sar[i];
            #pragma unroll
            for (int w = 0; w < NMS_WORDS; w++) {
                int j = (w << 5) + lane;
                bool sup = false;
                if (j < K_DETS && j > i) {
                    float lx = fmaxf(ix1, sx1[j]);
                    float ly = fmaxf(iy1, sy1[j]);
                    float rx = fminf(ix2, sx2[j]);
                    float ry = fminf(iy2, sy2[j]);
                    float iw = fmaxf(rx - lx, 0.0f);
                    float ih = fmaxf(ry - ly, 0.0f);
                    float inter = iw * ih;
                    float uni = ia + sar[j] - inter;
                    sup = (inter / fmaxf(uni, 1e-9f)) > 0.45f;
                }
                unsigned m = __ballot_sync(0xffffffffu, sup);
                if (lane == 0) s_mask[i * NMS_WORDS + w] = m;
            }
        }
    }
    __syncthreads();

    // --- Phase F: greedy scan, warp 0; lane w owns removal word w ---
    if (t < 32) {
        unsigned rm = 0;
        #pragma unroll
        for (int w = 0; w < NMS_WORDS; w++) {
            int j = (w << 5) + t;
            bool inv = (j < K_DETS) ? (svalid[j] == 0) : false;
            unsigned bword = __ballot_sync(0xffffffffu, inv);
            if (t == w) rm = bword;
        }
        unsigned cur = (t < NMS_WORDS) ? s_mask[t] : 0;
        for (int i = 0; i < K_DETS; i++) {
            unsigned nxt = (t < NMS_WORDS && i + 1 < K_DETS)
                           ? s_mask[(i + 1) * NMS_WORDS + t] : 0;
            unsigned word = __shfl_sync(0xffffffffu, rm, i >> 5);
            bool alive = !((word >> (i & 31)) & 1u);
            if (alive) rm |= cur;
            if (t == 0) s_kp[i] = alive ? 1 : 0;
            cur = nxt;
        }
    }
    __syncthreads();

    // --- Phase G: scalar outputs ---
    if (t < K_DETS) {
        int k = s_kp[t];
        float fx1 = k ? sx1[t] : 0.f, fy1 = k ? sy1[t] : 0.f;
        float fx2 = k ? sx2[t] : 0.f, fy2 = k ? sy2[t] : 0.f;
        out[OFF_BOXES + 4 * t + 0] = fx1;
        out[OFF_BOXES + 4 * t + 1] = fy1;
        out[OFF_BOXES + 4 * t + 2] = fx2;
        out[OFF_BOXES + 4 * t + 3] = fy2;
        out[OFF_SCORES + t] = k ? sscore[t] : 0.0f;
        int cv = 0;
        int idx = sidx[t];
        if (k && idx >= 0) cv = (int)g_cls[idx] + 1;
        out[OFF_CLASSES + t] = (float)cv;
        out[OFF_KEEP + t]    = k ? 1.0f : 0.0f;
        g_fbox[t] = make_float4(fx1, fy1, fx2, fy2);
        g_keep[t] = k;
    }
}

// ---------------------------------------------------------------------------
// Crops: 4 output pixels per thread (same row), float4 store.
// Crop 0 = full-image bilinear resize (ROI with box (0,0,1280,1280)).
__global__ void k_crops(const float* __restrict__ img, float* __restrict__ out) {
    int q = blockIdx.x * blockDim.x + threadIdx.x;   // 0..37631
    if (q >= CROP_ELEMS / 4) return;
    int b = blockIdx.y;
    int pix = q * 4;
    int c   = pix / CH_ELEMS;
    int rem = pix - c * CH_ELEMS;
    int yo  = rem / OUTSZ;
    int xo  = rem - yo * OUTSZ;

    float mean = c_mean[c], istd = c_istd[c];

    float x1, y1, x2, y2; int kpF;
    if (b == 0) {
        x1 = 0.f; y1 = 0.f; x2 = (float)IMG_W; y2 = (float)IMG_W; kpF = 1;
    } else {
        kpF = g_keep[b - 1];
        float4 bb = g_fbox[b - 1];
        x1 = bb.x; y1 = bb.y; x2 = bb.z; y2 = bb.w;
    }

    float4 r;
    if (!kpF) {
        float z = -mean * istd;
        r = make_float4(z, z, z, z);
    } else {
        const float inv = 1.0f / (float)OUTSZ;
        float dy = y2 - y1, dx = x2 - x1;
        float gy = ((float)yo + 0.5f) * inv;
        float ys = y1 - 0.5f + gy * dy;
        bool  vy = (ys >= -1.0f) && (ys <= (float)IMG_W);
        float yc = fminf(fmaxf(ys, 0.0f), (float)(IMG_W - 1));
        int   y0 = (int)floorf(yc);
        int   y1i = min(y0 + 1, IMG_W - 1);
        float ly = yc - (float)y0;
        const float* p0 = img + c * (IMG_W * IMG_W) + y0  * IMG_W;
        const float* p1 = img + c * (IMG_W * IMG_W) + y1i * IMG_W;

        float v[4];
        #pragma unroll
        for (int k = 0; k < 4; k++) {
            float gx = ((float)(xo + k) + 0.5f) * inv;
            float xs = x1 - 0.5f + gx * dx;
            float val = 0.0f;
            if (vy && xs >= -1.0f && xs <= (float)IMG_W) {
                float xc = fminf(fmaxf(xs, 0.0f), (float)(IMG_W - 1));
                int x0 = (int)floorf(xc);
                int x1i = min(x0 + 1, IMG_W - 1);
                float lx = xc - (float)x0;
                float v00 = p0[x0];
                float v01 = p0[x1i];
                float v10 = p1[x0];
                float v11 = p1[x1i];
                float top = v00 * (1.0f - lx) + v01 * lx;
                float bot = v10 * (1.0f - lx) + v11 * lx;
                val = top * (1.0f - ly) + bot * ly;
            }
            v[k] = (val - mean) * istd;
        }
        r = make_float4(v[0], v[1], v[2], v[3]);
    }
    ((float4*)(out + OFF_CROPS + (size_t)b * CROP_ELEMS))[q] = r;
}

// ---------------------------------------------------------------------------
extern "C" void kernel_launch(void* const* d_in, const int* in_sizes, int n_in,
                              void* d_out, int out_size) {
    const float* raw = (const float*)d_in[0];   // (1,85,100800)
    const float* img = (const float*)d_in[1];   // (1,3,1280,1280)
    float* out = (float*)d_out;

    k_score<<<(N_ANCHS / 4 + 255) / 256, 256>>>(raw);
    k_select_nms<<<1, 1024>>>(raw, out);
    dim3 g((CROP_ELEMS / 4 + 255) / 256, 301);
    k_crops<<<g, 256>>>(img, out);
}